// round 1
// baseline (speedup 1.0000x reference)
#include <cuda_runtime.h>

#define Dd     3
#define HID    64
#define WIDTH  64
#define BATCH  500000
#define BLOCKP (Dd * WIDTH)        // 192
#define P3N    (3 * BLOCKP + WIDTH) // 640

#define TPB 256
#define EPT 4

// Hypernet output, interleaved per hidden unit j:
//   g_params[2j]   = {W[j][0], W[j][1], W[j][2], B[j]}
//   g_params[2j+1] = {U[j][0], U[j][1], U[j][2], wu[j]}
__device__ float4 g_params[2 * WIDTH];
__device__ float  g_S;   // sum_j wu[j]

// ---------------------------------------------------------------------------
// Kernel 1: hypernet (1 block, 640 threads). Tiny; uses accurate tanhf.
// ---------------------------------------------------------------------------
__global__ void hyper_kernel(const float* __restrict__ t,
                             const float* __restrict__ fc1_w,
                             const float* __restrict__ fc1_b,
                             const float* __restrict__ fc2_w,
                             const float* __restrict__ fc2_b,
                             const float* __restrict__ fc3_w,
                             const float* __restrict__ fc3_b)
{
    __shared__ float p1[HID];
    __shared__ float p2[HID];
    __shared__ float p3[P3N];
    __shared__ float swu[WIDTH];

    const int tid = threadIdx.x;

    // stage 1: p1 = tanh(t * fc1_w + fc1_b)
    if (tid < HID) {
        p1[tid] = tanhf(t[0] * fc1_w[tid] + fc1_b[tid]);
    }
    __syncthreads();

    // stage 2: p2 = tanh(p1 @ fc2_w.T + fc2_b)
    if (tid < HID) {
        float acc = fc2_b[tid];
        const float* row = fc2_w + tid * HID;
        #pragma unroll 8
        for (int j = 0; j < HID; j++) acc = fmaf(p1[j], row[j], acc);
        p2[tid] = tanhf(acc);
    }
    __syncthreads();

    // stage 3: p3 = p2 @ fc3_w.T + fc3_b   (640 rows, one per thread)
    {
        float acc = fc3_b[tid];
        const float* row = fc3_w + tid * HID;
        #pragma unroll 8
        for (int j = 0; j < HID; j++) acc = fmaf(p2[j], row[j], acc);
        p3[tid] = acc;
    }
    __syncthreads();

    // assemble: W, B, U' = U*sigmoid(G), wu = sum_d W*U'
    if (tid < WIDTH) {
        const int j = tid;
        float w[3], u[3];
        float wu = 0.0f;
        #pragma unroll
        for (int d = 0; d < 3; d++) {
            w[d] = p3[3 * j + d];
            float ur = p3[BLOCKP + 3 * j + d];
            float g  = p3[2 * BLOCKP + 3 * j + d];
            float sg = 1.0f / (1.0f + expf(-g));
            u[d] = ur * sg;
            wu = fmaf(w[d], u[d], wu);
        }
        float b = p3[3 * BLOCKP + j];
        g_params[2 * j]     = make_float4(w[0], w[1], w[2], b);
        g_params[2 * j + 1] = make_float4(u[0], u[1], u[2], wu);
        swu[j] = wu;
    }
    __syncthreads();

    if (tid == 0) {
        float s = 0.0f;
        for (int j = 0; j < WIDTH; j++) s += swu[j];
        g_S = s;
    }
}

// ---------------------------------------------------------------------------
// Fast tanh: tanh(x) = 1 - 2/(exp(2x)+1), via ex2.approx + rcp.approx.
// ~1e-6 rel err; correct saturation at +/-inf.
// ---------------------------------------------------------------------------
__device__ __forceinline__ float ftanh(float x)
{
    float p = x * 2.885390082f;           // 2 * log2(e)
    float e;
    asm("ex2.approx.f32 %0, %1;" : "=f"(e) : "f"(p));
    float den = e + 1.0f;
    float r;
    asm("rcp.approx.f32 %0, %1;" : "=f"(r) : "f"(den));
    return fmaf(-2.0f, r, 1.0f);
}

// ---------------------------------------------------------------------------
// Kernel 2: main batch kernel. 4 elements/thread, float4 I/O.
// ---------------------------------------------------------------------------
__global__ void __launch_bounds__(TPB)
cnf_kernel(const float* __restrict__ z, float* __restrict__ out)
{
    __shared__ float4 sp[2 * WIDTH];

    const int tid = threadIdx.x;
    if (tid < 2 * WIDTH) sp[tid] = g_params[tid];
    __syncthreads();

    const float S = g_S;

    const int base = (blockIdx.x * TPB + tid) * EPT;
    if (base >= BATCH) return;   // BATCH % 4 == 0: all-or-nothing per thread

    // Load 4 elements of z (12 contiguous floats, 16B aligned)
    const float4* z4 = reinterpret_cast<const float4*>(z + (size_t)base * 3);
    float4 a0 = z4[0], a1 = z4[1], a2 = z4[2];
    float zx[EPT], zy[EPT], zz[EPT];
    zx[0] = a0.x; zy[0] = a0.y; zz[0] = a0.z;
    zx[1] = a0.w; zy[1] = a1.x; zz[1] = a1.y;
    zx[2] = a1.z; zy[2] = a1.w; zz[2] = a2.x;
    zx[3] = a2.y; zy[3] = a2.z; zz[3] = a2.w;

    float d0[EPT], d1[EPT], d2[EPT], hw[EPT];
    #pragma unroll
    for (int e = 0; e < EPT; e++) { d0[e] = 0.f; d1[e] = 0.f; d2[e] = 0.f; hw[e] = 0.f; }

    #pragma unroll 4
    for (int j = 0; j < WIDTH; j++) {
        const float4 wb = sp[2 * j];       // W0 W1 W2 B
        const float4 uw = sp[2 * j + 1];   // U0 U1 U2 wu
        #pragma unroll
        for (int e = 0; e < EPT; e++) {
            float pre = fmaf(zx[e], wb.x, fmaf(zy[e], wb.y, fmaf(zz[e], wb.z, wb.w)));
            float h = ftanh(pre);
            d0[e] = fmaf(h, uw.x, d0[e]);
            d1[e] = fmaf(h, uw.y, d1[e]);
            d2[e] = fmaf(h, uw.z, d2[e]);
            hw[e] = fmaf(h * h, uw.w, hw[e]);
        }
    }

    const float inv = 1.0f / (float)WIDTH;

    // dz_dt: 12 contiguous floats
    float4 o0 = make_float4(d0[0] * inv, d1[0] * inv, d2[0] * inv, d0[1] * inv);
    float4 o1 = make_float4(d1[1] * inv, d2[1] * inv, d0[2] * inv, d1[2] * inv);
    float4 o2 = make_float4(d2[2] * inv, d0[3] * inv, d1[3] * inv, d2[3] * inv);
    float4* o = reinterpret_cast<float4*>(out + (size_t)base * 3);
    o[0] = o0; o[1] = o1; o[2] = o2;

    // dlogp_z_dt = -trace = (hw - S)/WIDTH
    float4 lp = make_float4((hw[0] - S) * inv, (hw[1] - S) * inv,
                            (hw[2] - S) * inv, (hw[3] - S) * inv);
    *reinterpret_cast<float4*>(out + (size_t)(3 * BATCH) + base) = lp;
}

// ---------------------------------------------------------------------------
// Launch
// ---------------------------------------------------------------------------
extern "C" void kernel_launch(void* const* d_in, const int* in_sizes, int n_in,
                              void* d_out, int out_size)
{
    const float* t     = (const float*)d_in[0];
    const float* z     = (const float*)d_in[1];
    // d_in[2] = logp_z (unused by the math)
    const float* fc1_w = (const float*)d_in[3];
    const float* fc1_b = (const float*)d_in[4];
    const float* fc2_w = (const float*)d_in[5];
    const float* fc2_b = (const float*)d_in[6];
    const float* fc3_w = (const float*)d_in[7];
    const float* fc3_b = (const float*)d_in[8];
    float* out = (float*)d_out;

    hyper_kernel<<<1, P3N>>>(t, fc1_w, fc1_b, fc2_w, fc2_b, fc3_w, fc3_b);

    const int elems_per_block = TPB * EPT;
    const int grid = (BATCH + elems_per_block - 1) / elems_per_block;
    cnf_kernel<<<grid, TPB>>>(z, out);
}

// round 2
// speedup vs baseline: 1.6486x; 1.6486x over previous
#include <cuda_runtime.h>

#define Dd     3
#define HID    64
#define WIDTH  64
#define BATCH  500000
#define BLOCKP (Dd * WIDTH)         // 192
#define P3N    (3 * BLOCKP + WIDTH) // 640

#define TPB 256
#define EPT 4                        // 2 f32x2 pairs per thread

#define LOG2E2 2.8853900817779268f   // 2 * log2(e)

typedef unsigned long long ull;

// Params, packed-duplicated for f32x2 math. Per hidden unit j, 4 float4s:
//  [4j+0] = {W0s,W0s,W1s,W1s}   (Ws = W * 2log2e, tanh-input scale folded in)
//  [4j+1] = {W2s,W2s,Bs,Bs}
//  [4j+2] = {U0,U0,U1,U1}
//  [4j+3] = {U2,U2,wu,wu}
__device__ float4 g_p4[4 * WIDTH];
__device__ float  g_S;   // sum_j wu[j]

// ---------------------------------------------------------------------------
// f32x2 helpers (sm_103a packed fp32)
// ---------------------------------------------------------------------------
__device__ __forceinline__ ull ffma2(ull a, ull b, ull c) {
    ull d;
    asm("fma.rn.f32x2 %0, %1, %2, %3;" : "=l"(d) : "l"(a), "l"(b), "l"(c));
    return d;
}
__device__ __forceinline__ ull fmul2(ull a, ull b) {
    ull d;
    asm("mul.rn.f32x2 %0, %1, %2;" : "=l"(d) : "l"(a), "l"(b));
    return d;
}
__device__ __forceinline__ ull pack2(float lo, float hi) {
    ull d;
    asm("mov.b64 %0, {%1, %2};" : "=l"(d) : "f"(lo), "f"(hi));
    return d;
}
__device__ __forceinline__ void unpack2(ull v, float& lo, float& hi) {
    asm("mov.b64 {%0, %1}, %2;" : "=f"(lo), "=f"(hi) : "l"(v));
}
__device__ __forceinline__ float ex2f(float x) {
    float r;
    asm("ex2.approx.f32 %0, %1;" : "=f"(r) : "f"(x));
    return r;
}
__device__ __forceinline__ float rcpf(float x) {
    float r;
    asm("rcp.approx.f32 %0, %1;" : "=f"(r) : "f"(x));
    return r;
}

// ---------------------------------------------------------------------------
// Kernel 1: hypernet (1 block, 640 threads). Vectorized float4 row loads.
// ---------------------------------------------------------------------------
__global__ void hyper_kernel(const float* __restrict__ t,
                             const float* __restrict__ fc1_w,
                             const float* __restrict__ fc1_b,
                             const float* __restrict__ fc2_w,
                             const float* __restrict__ fc2_b,
                             const float* __restrict__ fc3_w,
                             const float* __restrict__ fc3_b)
{
    __shared__ float p1[HID];
    __shared__ float p2[HID];
    __shared__ float p3[P3N];
    __shared__ float swu[WIDTH];

    const int tid = threadIdx.x;

    // stage 1: p1 = tanh(t * fc1_w + fc1_b)
    if (tid < HID) {
        p1[tid] = tanhf(t[0] * fc1_w[tid] + fc1_b[tid]);
    }
    __syncthreads();

    // stage 2: p2 = tanh(p1 @ fc2_w.T + fc2_b)   (row-contiguous float4 loads)
    if (tid < HID) {
        const float4* row = reinterpret_cast<const float4*>(fc2_w + tid * HID);
        float a0 = 0.f, a1 = 0.f, a2 = 0.f, a3 = 0.f;
        #pragma unroll
        for (int i = 0; i < 16; i++) {
            float4 r = row[i];
            const float* pp = p1 + 4 * i;
            a0 = fmaf(r.x, pp[0], a0);
            a1 = fmaf(r.y, pp[1], a1);
            a2 = fmaf(r.z, pp[2], a2);
            a3 = fmaf(r.w, pp[3], a3);
        }
        p2[tid] = tanhf((a0 + a1) + (a2 + a3) + fc2_b[tid]);
    }
    __syncthreads();

    // stage 3: p3 = p2 @ fc3_w.T + fc3_b   (640 rows, one per thread)
    {
        const float4* row = reinterpret_cast<const float4*>(fc3_w + tid * HID);
        float a0 = 0.f, a1 = 0.f, a2 = 0.f, a3 = 0.f;
        #pragma unroll
        for (int i = 0; i < 16; i++) {
            float4 r = row[i];
            const float* pp = p2 + 4 * i;
            a0 = fmaf(r.x, pp[0], a0);
            a1 = fmaf(r.y, pp[1], a1);
            a2 = fmaf(r.z, pp[2], a2);
            a3 = fmaf(r.w, pp[3], a3);
        }
        p3[tid] = (a0 + a1) + (a2 + a3) + fc3_b[tid];
    }
    __syncthreads();

    // assemble: W, B, U' = U*sigmoid(G), wu = sum_d W*U'; fold 2log2e into W,B
    if (tid < WIDTH) {
        const int j = tid;
        float w[3], u[3];
        float wu = 0.0f;
        #pragma unroll
        for (int d = 0; d < 3; d++) {
            w[d] = p3[3 * j + d];
            float ur = p3[BLOCKP + 3 * j + d];
            float g  = p3[2 * BLOCKP + 3 * j + d];
            float sg = 1.0f / (1.0f + expf(-g));
            u[d] = ur * sg;
            wu = fmaf(w[d], u[d], wu);
        }
        float b = p3[3 * BLOCKP + j];
        float w0s = w[0] * LOG2E2, w1s = w[1] * LOG2E2;
        float w2s = w[2] * LOG2E2, bs  = b * LOG2E2;
        g_p4[4 * j + 0] = make_float4(w0s, w0s, w1s, w1s);
        g_p4[4 * j + 1] = make_float4(w2s, w2s, bs,  bs);
        g_p4[4 * j + 2] = make_float4(u[0], u[0], u[1], u[1]);
        g_p4[4 * j + 3] = make_float4(u[2], u[2], wu,  wu);
        swu[j] = wu;
    }
    __syncthreads();

    if (tid == 0) {
        float s = 0.0f;
        for (int j = 0; j < WIDTH; j++) s += swu[j];
        g_S = s;
    }
}

// ---------------------------------------------------------------------------
// Kernel 2: main batch kernel. 4 elements/thread as 2 f32x2 pairs.
// ---------------------------------------------------------------------------
__global__ void __launch_bounds__(TPB)
cnf_kernel(const float* __restrict__ z, float* __restrict__ out)
{
    __shared__ __align__(16) float4 sp4[4 * WIDTH];

    const int tid = threadIdx.x;
    if (tid < 4 * WIDTH) sp4[tid] = g_p4[tid];
    __syncthreads();

    const float S = g_S;

    const int base = (blockIdx.x * TPB + tid) * EPT;
    if (base >= BATCH) return;   // BATCH % 4 == 0

    // Load 4 elements of z (12 contiguous floats)
    const float4* z4 = reinterpret_cast<const float4*>(z + (size_t)base * 3);
    float4 a0 = z4[0], a1 = z4[1], a2 = z4[2];

    // Pack into f32x2 pairs: pair0 = elems {0,1}, pair1 = elems {2,3}
    ull zx2[2], zy2[2], zz2[2];
    zx2[0] = pack2(a0.x, a0.w);
    zy2[0] = pack2(a0.y, a1.x);
    zz2[0] = pack2(a0.z, a1.y);
    zx2[1] = pack2(a1.z, a2.y);
    zy2[1] = pack2(a1.w, a2.z);
    zz2[1] = pack2(a2.x, a2.w);

    ull d0[2], d1[2], d2[2], hw[2];
    #pragma unroll
    for (int p = 0; p < 2; p++) { d0[p] = 0ull; d1[p] = 0ull; d2[p] = 0ull; hw[p] = 0ull; }

    const ull cN2 = pack2(-2.0f, -2.0f);
    const ull cP1 = pack2( 1.0f,  1.0f);

    const ulonglong2* spp = reinterpret_cast<const ulonglong2*>(sp4);

    #pragma unroll 8
    for (int j = 0; j < WIDTH; j++) {
        const ulonglong2 q0 = spp[4 * j + 0];  // {W0s,W0s},{W1s,W1s}
        const ulonglong2 q1 = spp[4 * j + 1];  // {W2s,W2s},{Bs,Bs}
        const ulonglong2 q2 = spp[4 * j + 2];  // {U0,U0},{U1,U1}
        const ulonglong2 q3 = spp[4 * j + 3];  // {U2,U2},{wu,wu}
        #pragma unroll
        for (int p = 0; p < 2; p++) {
            ull pre = ffma2(zz2[p], q1.x, q1.y);       // pre-activation * 2log2e
            pre = ffma2(zy2[p], q0.y, pre);
            pre = ffma2(zx2[p], q0.x, pre);
            float plo, phi;
            unpack2(pre, plo, phi);
            float rlo = rcpf(ex2f(plo) + 1.0f);        // 1/(e^{2x}+1)
            float rhi = rcpf(ex2f(phi) + 1.0f);
            ull r2 = pack2(rlo, rhi);
            ull h2 = ffma2(r2, cN2, cP1);              // h = 1 - 2r = tanh
            d0[p] = ffma2(h2, q2.x, d0[p]);
            d1[p] = ffma2(h2, q2.y, d1[p]);
            d2[p] = ffma2(h2, q3.x, d2[p]);
            ull hh = fmul2(h2, h2);
            hw[p] = ffma2(hh, q3.y, hw[p]);
        }
    }

    const float inv = 1.0f / (float)WIDTH;

    float d0e[4], d1e[4], d2e[4], hwe[4];
    unpack2(d0[0], d0e[0], d0e[1]); unpack2(d0[1], d0e[2], d0e[3]);
    unpack2(d1[0], d1e[0], d1e[1]); unpack2(d1[1], d1e[2], d1e[3]);
    unpack2(d2[0], d2e[0], d2e[1]); unpack2(d2[1], d2e[2], d2e[3]);
    unpack2(hw[0], hwe[0], hwe[1]); unpack2(hw[1], hwe[2], hwe[3]);

    // dz_dt: 12 contiguous floats
    float4 o0 = make_float4(d0e[0] * inv, d1e[0] * inv, d2e[0] * inv, d0e[1] * inv);
    float4 o1 = make_float4(d1e[1] * inv, d2e[1] * inv, d0e[2] * inv, d1e[2] * inv);
    float4 o2 = make_float4(d2e[2] * inv, d0e[3] * inv, d1e[3] * inv, d2e[3] * inv);
    float4* o = reinterpret_cast<float4*>(out + (size_t)base * 3);
    o[0] = o0; o[1] = o1; o[2] = o2;

    // dlogp_z_dt = -trace = (sum h^2 wu - S)/WIDTH
    float4 lp = make_float4((hwe[0] - S) * inv, (hwe[1] - S) * inv,
                            (hwe[2] - S) * inv, (hwe[3] - S) * inv);
    *reinterpret_cast<float4*>(out + (size_t)(3 * BATCH) + base) = lp;
}

// ---------------------------------------------------------------------------
// Launch
// ---------------------------------------------------------------------------
extern "C" void kernel_launch(void* const* d_in, const int* in_sizes, int n_in,
                              void* d_out, int out_size)
{
    const float* t     = (const float*)d_in[0];
    const float* z     = (const float*)d_in[1];
    // d_in[2] = logp_z (unused)
    const float* fc1_w = (const float*)d_in[3];
    const float* fc1_b = (const float*)d_in[4];
    const float* fc2_w = (const float*)d_in[5];
    const float* fc2_b = (const float*)d_in[6];
    const float* fc3_w = (const float*)d_in[7];
    const float* fc3_b = (const float*)d_in[8];
    float* out = (float*)d_out;

    hyper_kernel<<<1, P3N>>>(t, fc1_w, fc1_b, fc2_w, fc2_b, fc3_w, fc3_b);

    const int elems_per_block = TPB * EPT;
    const int grid = (BATCH + elems_per_block - 1) / elems_per_block;
    cnf_kernel<<<grid, TPB>>>(z, out);
}

// round 3
// speedup vs baseline: 2.3454x; 1.4227x over previous
#include <cuda_runtime.h>

#define Dd     3
#define HID    64
#define WIDTH  64
#define BATCH  500000
#define BLOCKP (Dd * WIDTH)         // 192
#define P3N    (3 * BLOCKP + WIDTH) // 640

#define TPB 128
#define EPT 8                        // 4 f32x2 pairs per thread
#define NPAIR 4

typedef unsigned long long ull;

// Params, packed-duplicated for f32x2 math. Per hidden unit j, 4 float4s:
//  [4j+0] = {W0,W0,W1,W1}
//  [4j+1] = {W2,W2,B,B}
//  [4j+2] = {U0,U0,U1,U1}
//  [4j+3] = {U2,U2,wu,wu}
__device__ float4 g_p4[4 * WIDTH];

// ---------------------------------------------------------------------------
// f32x2 / misc helpers
// ---------------------------------------------------------------------------
__device__ __forceinline__ ull ffma2(ull a, ull b, ull c) {
    ull d;
    asm("fma.rn.f32x2 %0, %1, %2, %3;" : "=l"(d) : "l"(a), "l"(b), "l"(c));
    return d;
}
__device__ __forceinline__ ull fmul2(ull a, ull b) {
    ull d;
    asm("mul.rn.f32x2 %0, %1, %2;" : "=l"(d) : "l"(a), "l"(b));
    return d;
}
__device__ __forceinline__ ull fadd2(ull a, ull b) {
    ull d;
    asm("add.rn.f32x2 %0, %1, %2;" : "=l"(d) : "l"(a), "l"(b));
    return d;
}
__device__ __forceinline__ ull pack2(float lo, float hi) {
    ull d;
    asm("mov.b64 %0, {%1, %2};" : "=l"(d) : "f"(lo), "f"(hi));
    return d;
}
__device__ __forceinline__ void unpack2(ull v, float& lo, float& hi) {
    asm("mov.b64 {%0, %1}, %2;" : "=f"(lo), "=f"(hi) : "l"(v));
}
__device__ __forceinline__ float tanha(float x) {
    float r;
    asm("tanh.approx.f32 %0, %1;" : "=f"(r) : "f"(x));
    return r;
}

// ---------------------------------------------------------------------------
// Kernel 1: hypernet, 4 blocks. Block b produces j in [16b, 16b+16).
// Stages 1-2 (tiny) are recomputed per block; stage 3 rows are partitioned
// exactly (160 rows per block, no duplication).
// ---------------------------------------------------------------------------
__global__ void __launch_bounds__(256)
hyper_kernel(const float* __restrict__ t,
             const float* __restrict__ fc1_w,
             const float* __restrict__ fc1_b,
             const float* __restrict__ fc2_w,
             const float* __restrict__ fc2_b,
             const float* __restrict__ fc3_w,
             const float* __restrict__ fc3_b)
{
    __shared__ float p1[HID];
    __shared__ float p2[HID];
    __shared__ float p3loc[160];

    const int tid = threadIdx.x;
    const int b   = blockIdx.x;

    // stage 1
    if (tid < HID) {
        p1[tid] = tanhf(t[0] * fc1_w[tid] + fc1_b[tid]);
    }
    __syncthreads();

    // stage 2
    if (tid < HID) {
        const float4* row = reinterpret_cast<const float4*>(fc2_w + tid * HID);
        float a0 = 0.f, a1 = 0.f, a2 = 0.f, a3 = 0.f;
        #pragma unroll
        for (int i = 0; i < 16; i++) {
            float4 r = row[i];
            const float* pp = p1 + 4 * i;
            a0 = fmaf(r.x, pp[0], a0);
            a1 = fmaf(r.y, pp[1], a1);
            a2 = fmaf(r.z, pp[2], a2);
            a3 = fmaf(r.w, pp[3], a3);
        }
        p2[tid] = tanhf((a0 + a1) + (a2 + a3) + fc2_b[tid]);
    }
    __syncthreads();

    // stage 3: the 160 fc3 rows this block's j-slice needs.
    // local rows: [0,48) -> W rows 48b+r; [48,96) -> U rows 192+48b+(r-48);
    // [96,144) -> G rows 384+48b+(r-96); [144,160) -> B rows 576+16b+(r-144)
    if (tid < 160) {
        int grow;
        if      (tid < 48)  grow = 48 * b + tid;
        else if (tid < 96)  grow = BLOCKP + 48 * b + (tid - 48);
        else if (tid < 144) grow = 2 * BLOCKP + 48 * b + (tid - 96);
        else                grow = 3 * BLOCKP + 16 * b + (tid - 144);

        const float4* row = reinterpret_cast<const float4*>(fc3_w + grow * HID);
        float a0 = 0.f, a1 = 0.f, a2 = 0.f, a3 = 0.f;
        #pragma unroll
        for (int i = 0; i < 16; i++) {
            float4 r = row[i];
            const float* pp = p2 + 4 * i;
            a0 = fmaf(r.x, pp[0], a0);
            a1 = fmaf(r.y, pp[1], a1);
            a2 = fmaf(r.z, pp[2], a2);
            a3 = fmaf(r.w, pp[3], a3);
        }
        p3loc[tid] = (a0 + a1) + (a2 + a3) + fc3_b[grow];
    }
    __syncthreads();

    // assemble this block's 16 j's
    if (tid < 16) {
        const int j = 16 * b + tid;
        float w[3], u[3];
        #pragma unroll
        for (int d = 0; d < 3; d++) {
            w[d] = p3loc[3 * tid + d];
            float ur = p3loc[48 + 3 * tid + d];
            float g  = p3loc[96 + 3 * tid + d];
            float sg = 1.0f / (1.0f + expf(-g));
            u[d] = ur * sg;
        }
        float wu = fmaf(w[0], u[0], fmaf(w[1], u[1], w[2] * u[2]));
        float bb = p3loc[144 + tid];
        g_p4[4 * j + 0] = make_float4(w[0], w[0], w[1], w[1]);
        g_p4[4 * j + 1] = make_float4(w[2], w[2], bb,  bb);
        g_p4[4 * j + 2] = make_float4(u[0], u[0], u[1], u[1]);
        g_p4[4 * j + 3] = make_float4(u[2], u[2], wu,  wu);
    }
}

// ---------------------------------------------------------------------------
// Kernel 2: main batch kernel. 8 elements/thread as 4 f32x2 pairs.
// ---------------------------------------------------------------------------
__global__ void __launch_bounds__(TPB)
cnf_kernel(const float* __restrict__ z, float* __restrict__ out)
{
    __shared__ __align__(16) float4 sp4[4 * WIDTH];

    const int tid = threadIdx.x;
    #pragma unroll
    for (int i = tid; i < 4 * WIDTH; i += TPB) sp4[i] = g_p4[i];
    __syncthreads();

    const int base = (blockIdx.x * TPB + tid) * EPT;
    if (base >= BATCH) return;   // BATCH % 8 == 0: all-or-nothing per thread

    // Load 8 elements of z (24 contiguous floats)
    const float4* z4 = reinterpret_cast<const float4*>(z + (size_t)base * 3);
    float f[24];
    #pragma unroll
    for (int i = 0; i < 6; i++) {
        float4 v = z4[i];
        f[4 * i + 0] = v.x; f[4 * i + 1] = v.y;
        f[4 * i + 2] = v.z; f[4 * i + 3] = v.w;
    }
    // pair p covers elements {2p, 2p+1}
    ull zx2[NPAIR], zy2[NPAIR], zz2[NPAIR];
    #pragma unroll
    for (int p = 0; p < NPAIR; p++) {
        zx2[p] = pack2(f[6 * p + 0], f[6 * p + 3]);
        zy2[p] = pack2(f[6 * p + 1], f[6 * p + 4]);
        zz2[p] = pack2(f[6 * p + 2], f[6 * p + 5]);
    }

    ull d0[NPAIR], d1[NPAIR], d2[NPAIR], hw[NPAIR];
    #pragma unroll
    for (int p = 0; p < NPAIR; p++) { d0[p] = 0; d1[p] = 0; d2[p] = 0; hw[p] = 0; }
    ull sacc = 0;   // accumulates {S, S}

    const ulonglong2* spp = reinterpret_cast<const ulonglong2*>(sp4);

    #pragma unroll 4
    for (int j = 0; j < WIDTH; j++) {
        const ulonglong2 q0 = spp[4 * j + 0];  // {W0,W0},{W1,W1}
        const ulonglong2 q1 = spp[4 * j + 1];  // {W2,W2},{B,B}
        const ulonglong2 q2 = spp[4 * j + 2];  // {U0,U0},{U1,U1}
        const ulonglong2 q3 = spp[4 * j + 3];  // {U2,U2},{wu,wu}
        sacc = fadd2(sacc, q3.y);
        #pragma unroll
        for (int p = 0; p < NPAIR; p++) {
            ull pre = ffma2(zz2[p], q1.x, q1.y);
            pre = ffma2(zy2[p], q0.y, pre);
            pre = ffma2(zx2[p], q0.x, pre);
            float plo, phi;
            unpack2(pre, plo, phi);
            ull h2 = pack2(tanha(plo), tanha(phi));
            d0[p] = ffma2(h2, q2.x, d0[p]);
            d1[p] = ffma2(h2, q2.y, d1[p]);
            d2[p] = ffma2(h2, q3.x, d2[p]);
            ull hh = fmul2(h2, h2);
            hw[p] = ffma2(hh, q3.y, hw[p]);
        }
    }

    const float inv = 1.0f / (float)WIDTH;
    float S, Sdup;
    unpack2(sacc, S, Sdup);

    float od[24], lp[8];
    #pragma unroll
    for (int p = 0; p < NPAIR; p++) {
        float a, b2;
        unpack2(d0[p], a, b2); od[6 * p + 0] = a * inv; od[6 * p + 3] = b2 * inv;
        unpack2(d1[p], a, b2); od[6 * p + 1] = a * inv; od[6 * p + 4] = b2 * inv;
        unpack2(d2[p], a, b2); od[6 * p + 2] = a * inv; od[6 * p + 5] = b2 * inv;
        unpack2(hw[p], a, b2);
        lp[2 * p + 0] = (a  - S) * inv;
        lp[2 * p + 1] = (b2 - S) * inv;
    }

    float4* o = reinterpret_cast<float4*>(out + (size_t)base * 3);
    #pragma unroll
    for (int i = 0; i < 6; i++)
        o[i] = make_float4(od[4 * i], od[4 * i + 1], od[4 * i + 2], od[4 * i + 3]);

    float4* ol = reinterpret_cast<float4*>(out + (size_t)(3 * BATCH) + base);
    ol[0] = make_float4(lp[0], lp[1], lp[2], lp[3]);
    ol[1] = make_float4(lp[4], lp[5], lp[6], lp[7]);
}

// ---------------------------------------------------------------------------
// Launch
// ---------------------------------------------------------------------------
extern "C" void kernel_launch(void* const* d_in, const int* in_sizes, int n_in,
                              void* d_out, int out_size)
{
    const float* t     = (const float*)d_in[0];
    const float* z     = (const float*)d_in[1];
    // d_in[2] = logp_z (unused)
    const float* fc1_w = (const float*)d_in[3];
    const float* fc1_b = (const float*)d_in[4];
    const float* fc2_w = (const float*)d_in[5];
    const float* fc2_b = (const float*)d_in[6];
    const float* fc3_w = (const float*)d_in[7];
    const float* fc3_b = (const float*)d_in[8];
    float* out = (float*)d_out;

    hyper_kernel<<<4, 256>>>(t, fc1_w, fc1_b, fc2_w, fc2_b, fc3_w, fc3_b);

    const int elems_per_block = TPB * EPT;                      // 1024
    const int grid = (BATCH + elems_per_block - 1) / elems_per_block;  // 489
    cnf_kernel<<<grid, TPB>>>(z, out);
}